// round 6
// baseline (speedup 1.0000x reference)
#include <cuda_runtime.h>
#include <cuda_fp16.h>
#include <cstdint>

#define DI __device__ __forceinline__

// ---------------- problem sizes (fixed by setup_inputs) ----------------
constexpr int B_ = 4, S_ = 2048, I_ = 4096, O_ = 4096;
constexpr int M_ = B_ * S_;            // 8192
constexpr int NC_ = 40;                // cherries per row
constexpr int PACKED_ = (I_ - NC_) / 2;// 2028 packed bytes (one per int32)
constexpr int NG_ = 32;                // scale groups of 128

// scratch (device globals: allocation-free rule)
__device__ __half g_Xh[(size_t)M_ * I_]; // x rounded to fp16
__device__ __half g_Wh[(size_t)O_ * I_]; // dequantized weight fp16

// ---------------- PTX helpers (plain-sm_100 safe) ----------------
DI uint32_t smem_u32(const void* p) {
    uint32_t r;
    asm("{ .reg .u64 t; cvta.to.shared.u64 t, %1; cvt.u32.u64 %0, t; }" : "=r"(r) : "l"(p));
    return r;
}
DI void cp_async16(uint32_t dst, const void* src) {
    asm volatile("cp.async.cg.shared.global [%0], [%1], 16;" :: "r"(dst), "l"(src));
}
DI void cp_commit() { asm volatile("cp.async.commit_group;"); }
DI void cp_wait1()  { asm volatile("cp.async.wait_group 1;"); }
DI void ldmatrix_x4(uint32_t* r, uint32_t addr) {
    asm volatile("ldmatrix.sync.aligned.m8n8.x4.shared.b16 {%0,%1,%2,%3}, [%4];"
                 : "=r"(r[0]), "=r"(r[1]), "=r"(r[2]), "=r"(r[3]) : "r"(addr));
}
DI void mma_16816(float* c, const uint32_t* a, uint32_t b0, uint32_t b1) {
    asm volatile(
        "mma.sync.aligned.m16n8k16.row.col.f32.f16.f16.f32 "
        "{%0,%1,%2,%3}, {%4,%5,%6,%7}, {%8,%9}, {%0,%1,%2,%3};"
        : "+f"(c[0]), "+f"(c[1]), "+f"(c[2]), "+f"(c[3])
        : "r"(a[0]), "r"(a[1]), "r"(a[2]), "r"(a[3]), "r"(b0), "r"(b1));
}

// ---------------- kernel 1: x fp32 -> fp16 ----------------
__global__ void cvt_x_kernel(const float* __restrict__ x) {
    size_t i = (size_t)blockIdx.x * blockDim.x + threadIdx.x;  // 8 floats each
    float4 v0 = ((const float4*)x)[2 * i];
    float4 v1 = ((const float4*)x)[2 * i + 1];
    __half2 h0 = __floats2half2_rn(v0.x, v0.y);
    __half2 h1 = __floats2half2_rn(v0.z, v0.w);
    __half2 h2 = __floats2half2_rn(v1.x, v1.y);
    __half2 h3 = __floats2half2_rn(v1.z, v1.w);
    uint4 o;
    o.x = *(uint32_t*)&h0; o.y = *(uint32_t*)&h1;
    o.z = *(uint32_t*)&h2; o.w = *(uint32_t*)&h3;
    ((uint4*)g_Xh)[i] = o;
}

// ---------------- kernel 2: dequant + cherry scatter -> fp16 ----------------
__global__ void dequant_kernel(const int* __restrict__ qw,
                               const float* __restrict__ sc,
                               const int* __restrict__ ci,
                               const float* __restrict__ cw) {
    __shared__ int   s_idx[NC_];
    __shared__ float s_wv[NC_];
    __shared__ int   s_si[NC_];
    __shared__ float s_sw[NC_];
    __shared__ float s_sc[NG_];

    int row = blockIdx.x, tid = threadIdx.x;
    if (tid < NC_) { s_idx[tid] = ci[(size_t)row * NC_ + tid]; s_wv[tid] = cw[(size_t)row * NC_ + tid]; }
    if (tid < NG_) { s_sc[tid] = sc[(size_t)row * NG_ + tid]; }
    __syncthreads();
    if (tid < NC_) {
        int my = s_idx[tid], rk = 0;
        #pragma unroll
        for (int u = 0; u < NC_; u++) rk += (s_idx[u] < my);   // indices unique
        s_si[rk] = my; s_sw[rk] = s_wv[tid];
    }
    __syncthreads();

    const int* qrow = qw + (size_t)row * PACKED_;
    __half* wrow = g_Wh + (size_t)row * I_;

    int c0 = tid * 32;
    int lo = 0, hi = NC_;                       // lower_bound(c0) on sorted cherries
    while (lo < hi) { int mid = (lo + hi) >> 1; if (s_si[mid] < c0) lo = mid + 1; else hi = mid; }
    int k = lo;

    #pragma unroll
    for (int g = 0; g < 4; g++) {
        __half h[8];
        #pragma unroll
        for (int e = 0; e < 8; e++) {
            int c = c0 + g * 8 + e;
            float v;
            if (k < NC_ && s_si[k] == c) { v = s_sw[k]; k++; }
            else {
                int j = c - k;                              // normal idx, ascending fill
                int byte = qrow[j >> 1];
                int nib = (byte >> ((j & 1) * 4)) & 0xF;    // low nibble first
                v = (float)(nib - 8) * s_sc[j >> 7];        // (+QMIN) * group scale
            }
            h[e] = __float2half_rn(v);
        }
        uint4 o;
        o.x = *(uint32_t*)&h[0]; o.y = *(uint32_t*)&h[2];
        o.z = *(uint32_t*)&h[4]; o.w = *(uint32_t*)&h[6];
        *(uint4*)(wrow + c0 + g * 8) = o;
    }
}

// ---------------- kernel 3: multistage fp16 mma.sync GEMM ----------------
// out[8192,4096] = Xh * Wh^T + bias.  CTA tile 128x256, BK=64, 3 stages.
// 256 threads = 8 warps in a 2(m) x 4(n) grid of 64x64 warp tiles.
// Per K-chunk ldmatrix traffic: A*4 + B*2 = 128 KB for 4.19 MFLOP
// (0.0305 B/FLOP vs 0.0458 for the 712us 64x32-tile version).
constexpr int BM = 128, BN = 256, BK = 64;       // BK in halves (128 B/row)
constexpr int STAGES = 3;
constexpr int KT = I_ / BK;                       // 64 k-iterations
constexpr int A_BYTES = BM * BK * 2;              // 16 KB
constexpr int B_BYTES = BN * BK * 2;              // 32 KB
constexpr int STAGE_BYTES = A_BYTES + B_BYTES;    // 48 KB
constexpr int SMEM_BYTES = STAGES * STAGE_BYTES;  // 144 KB

__global__ void __launch_bounds__(256, 1)
gemm_f16(const float* __restrict__ bias, float* __restrict__ out) {
    extern __shared__ char smem[];
    const uint32_t smem_base = smem_u32(smem);

    const int tid = threadIdx.x;
    const int lane = tid & 31, wid = tid >> 5;
    const int warp_m = wid >> 2;                 // 0..1 (64 rows each)
    const int warp_n = wid & 3;                  // 0..3 (64 cols each)
    const int bn = blockIdx.x, bm = blockIdx.y;

    const __half* gA = g_Xh + (size_t)bm * BM * I_;
    const __half* gB = g_Wh + (size_t)bn * BN * I_;

    // ---- stage loader: A = 1024 chunks of 16B, B = 2048 chunks ----
    auto load_stage = [&](int s, int kt) {
        const int k0 = kt * BK;
        const uint32_t aBase = smem_base + s * STAGE_BYTES;
        const uint32_t bBase = aBase + A_BYTES;
        #pragma unroll
        for (int i = 0; i < 4; i++) {
            int chunk = i * 256 + tid;           // 0..1023
            int r = chunk >> 3, c = chunk & 7;
            uint32_t off = (uint32_t)((r * 8 + (c ^ (r & 7))) << 4);
            cp_async16(aBase + off, gA + (size_t)r * I_ + k0 + c * 8);
        }
        #pragma unroll
        for (int i = 0; i < 8; i++) {
            int chunk = i * 256 + tid;           // 0..2047
            int r = chunk >> 3, c = chunk & 7;
            uint32_t off = (uint32_t)((r * 8 + (c ^ (r & 7))) << 4);
            cp_async16(bBase + off, gB + (size_t)r * I_ + k0 + c * 8);
        }
    };

    float acc[4][8][4];
    #pragma unroll
    for (int mt = 0; mt < 4; mt++)
        #pragma unroll
        for (int nt = 0; nt < 8; nt++)
            #pragma unroll
            for (int e = 0; e < 4; e++) acc[mt][nt][e] = 0.f;

    // prologue: fill stages 0..STAGES-2
    #pragma unroll
    for (int s = 0; s < STAGES - 1; s++) { load_stage(s, s); cp_commit(); }
    cp_wait1();
    __syncthreads();

    for (int kt = 0; kt < KT; kt++) {
        int nxt = kt + STAGES - 1;
        if (nxt < KT) load_stage(nxt % STAGES, nxt);
        cp_commit();

        // ---- compute on stage kt % STAGES ----
        const uint32_t aStage = smem_base + (kt % STAGES) * STAGE_BYTES;
        const uint32_t bStage = aStage + A_BYTES;
        #pragma unroll
        for (int ks = 0; ks < BK / 16; ks++) {
            uint32_t a[4][4];
            #pragma unroll
            for (int mt = 0; mt < 4; mt++) {
                int r = warp_m * 64 + mt * 16 + (lane & 15);
                int c = ks * 2 + (lane >> 4);
                ldmatrix_x4(a[mt], aStage + (uint32_t)((r * 8 + (c ^ (r & 7))) << 4));
            }
            uint32_t b[4][4];
            #pragma unroll
            for (int bi = 0; bi < 4; bi++) {     // covers n-tiles 2bi, 2bi+1
                int r = warp_n * 64 + (2 * bi + (lane >> 4)) * 8 + (lane & 7);
                int c = ks * 2 + ((lane >> 3) & 1);
                ldmatrix_x4(b[bi], bStage + (uint32_t)((r * 8 + (c ^ (r & 7))) << 4));
            }
            #pragma unroll
            for (int mt = 0; mt < 4; mt++)
                #pragma unroll
                for (int nt = 0; nt < 8; nt++)
                    mma_16816(acc[mt][nt], a[mt], b[nt >> 1][2 * (nt & 1)], b[nt >> 1][2 * (nt & 1) + 1]);
        }

        cp_wait1();
        __syncthreads();
    }

    // ---- epilogue: add bias, store fp32 ----
    #pragma unroll
    for (int nt = 0; nt < 8; nt++) {
        int col = bn * BN + warp_n * 64 + nt * 8 + (lane & 3) * 2;
        float2 bv = *(const float2*)(bias + col);
        #pragma unroll
        for (int mt = 0; mt < 4; mt++) {
            int row = bm * BM + warp_m * 64 + mt * 16 + (lane >> 2);
            float2 v0 = { acc[mt][nt][0] + bv.x, acc[mt][nt][1] + bv.y };
            float2 v1 = { acc[mt][nt][2] + bv.x, acc[mt][nt][3] + bv.y };
            *(float2*)(out + (size_t)row * O_ + col)       = v0;
            *(float2*)(out + (size_t)(row + 8) * O_ + col) = v1;
        }
    }
}

// ---------------- launch ----------------
extern "C" void kernel_launch(void* const* d_in, const int* in_sizes, int n_in,
                              void* d_out, int out_size) {
    const float* x    = (const float*)d_in[0];
    const int*   qw   = (const int*)d_in[1];
    const float* sc   = (const float*)d_in[2];
    const int*   ci   = (const int*)d_in[3];
    const float* cw   = (const float*)d_in[4];
    const float* bias = (const float*)d_in[5];
    float* out = (float*)d_out;

    cudaFuncSetAttribute(gemm_f16, cudaFuncAttributeMaxDynamicSharedMemorySize, SMEM_BYTES);

    // 1) x -> fp16 (8 floats per thread)
    cvt_x_kernel<<<(M_ * I_) / 8 / 256, 256>>>(x);
    // 2) dequant + cherry scatter -> fp16 (one block per output row)
    dequant_kernel<<<O_, 128>>>(qw, sc, ci, cw);
    // 3) fp16 tensor-core GEMM + bias
    gemm_f16<<<dim3(O_ / BN, M_ / BM), 256, SMEM_BYTES>>>(bias, out);
}

// round 7
// speedup vs baseline: 1.1238x; 1.1238x over previous
#include <cuda_runtime.h>
#include <cuda_fp16.h>
#include <cstdint>

#define DI __device__ __forceinline__

// ---------------- problem sizes (fixed by setup_inputs) ----------------
constexpr int B_ = 4, S_ = 2048, I_ = 4096, O_ = 4096;
constexpr int M_ = B_ * S_;            // 8192
constexpr int NC_ = 40;                // cherries per row
constexpr int PACKED_ = (I_ - NC_) / 2;// 2028 packed bytes (one per int32)
constexpr int NG_ = 32;                // scale groups of 128

// scratch (device globals: allocation-free rule)
__device__ __half g_Xh[(size_t)M_ * I_]; // x rounded to fp16
__device__ __half g_Wh[(size_t)O_ * I_]; // dequantized weight fp16

// ---------------- PTX helpers (plain-sm_100 safe) ----------------
DI uint32_t smem_u32(const void* p) {
    uint32_t r;
    asm("{ .reg .u64 t; cvta.to.shared.u64 t, %1; cvt.u32.u64 %0, t; }" : "=r"(r) : "l"(p));
    return r;
}
DI void cp_async16(uint32_t dst, const void* src) {
    asm volatile("cp.async.cg.shared.global [%0], [%1], 16;" :: "r"(dst), "l"(src));
}
DI void cp_commit() { asm volatile("cp.async.commit_group;"); }
DI void cp_wait1()  { asm volatile("cp.async.wait_group 1;"); }
DI void ldmatrix_x4(uint32_t* r, uint32_t addr) {
    asm volatile("ldmatrix.sync.aligned.m8n8.x4.shared.b16 {%0,%1,%2,%3}, [%4];"
                 : "=r"(r[0]), "=r"(r[1]), "=r"(r[2]), "=r"(r[3]) : "r"(addr));
}
DI void mma_16816(float* c, const uint32_t* a, uint32_t b0, uint32_t b1) {
    asm volatile(
        "mma.sync.aligned.m16n8k16.row.col.f32.f16.f16.f32 "
        "{%0,%1,%2,%3}, {%4,%5,%6,%7}, {%8,%9}, {%0,%1,%2,%3};"
        : "+f"(c[0]), "+f"(c[1]), "+f"(c[2]), "+f"(c[3])
        : "r"(a[0]), "r"(a[1]), "r"(a[2]), "r"(a[3]), "r"(b0), "r"(b1));
}

// ---------------- kernel 0: profiler-alignment shim (no-op) ----------------
__global__ void shim_kernel() {}

// ---------------- kernel 1: x fp32 -> fp16 ----------------
__global__ void cvt_x_kernel(const float* __restrict__ x) {
    size_t i = (size_t)blockIdx.x * blockDim.x + threadIdx.x;  // 8 floats each
    float4 v0 = ((const float4*)x)[2 * i];
    float4 v1 = ((const float4*)x)[2 * i + 1];
    __half2 h0 = __floats2half2_rn(v0.x, v0.y);
    __half2 h1 = __floats2half2_rn(v0.z, v0.w);
    __half2 h2 = __floats2half2_rn(v1.x, v1.y);
    __half2 h3 = __floats2half2_rn(v1.z, v1.w);
    uint4 o;
    o.x = *(uint32_t*)&h0; o.y = *(uint32_t*)&h1;
    o.z = *(uint32_t*)&h2; o.w = *(uint32_t*)&h3;
    ((uint4*)g_Xh)[i] = o;
}

// ---------------- kernel 2: dequant + cherry scatter -> fp16 ----------------
__global__ void dequant_kernel(const int* __restrict__ qw,
                               const float* __restrict__ sc,
                               const int* __restrict__ ci,
                               const float* __restrict__ cw) {
    __shared__ int   s_idx[NC_];
    __shared__ float s_wv[NC_];
    __shared__ int   s_si[NC_];
    __shared__ float s_sw[NC_];
    __shared__ float s_sc[NG_];

    int row = blockIdx.x, tid = threadIdx.x;
    if (tid < NC_) { s_idx[tid] = ci[(size_t)row * NC_ + tid]; s_wv[tid] = cw[(size_t)row * NC_ + tid]; }
    if (tid < NG_) { s_sc[tid] = sc[(size_t)row * NG_ + tid]; }
    __syncthreads();
    if (tid < NC_) {
        int my = s_idx[tid], rk = 0;
        #pragma unroll
        for (int u = 0; u < NC_; u++) rk += (s_idx[u] < my);   // indices unique
        s_si[rk] = my; s_sw[rk] = s_wv[tid];
    }
    __syncthreads();

    const int* qrow = qw + (size_t)row * PACKED_;
    __half* wrow = g_Wh + (size_t)row * I_;

    int c0 = tid * 32;
    int lo = 0, hi = NC_;                       // lower_bound(c0) on sorted cherries
    while (lo < hi) { int mid = (lo + hi) >> 1; if (s_si[mid] < c0) lo = mid + 1; else hi = mid; }
    int k = lo;

    #pragma unroll
    for (int g = 0; g < 4; g++) {
        __half h[8];
        #pragma unroll
        for (int e = 0; e < 8; e++) {
            int c = c0 + g * 8 + e;
            float v;
            if (k < NC_ && s_si[k] == c) { v = s_sw[k]; k++; }
            else {
                int j = c - k;                              // normal idx, ascending fill
                int byte = qrow[j >> 1];
                int nib = (byte >> ((j & 1) * 4)) & 0xF;    // low nibble first
                v = (float)(nib - 8) * s_sc[j >> 7];        // (+QMIN) * group scale
            }
            h[e] = __float2half_rn(v);
        }
        uint4 o;
        o.x = *(uint32_t*)&h[0]; o.y = *(uint32_t*)&h[2];
        o.z = *(uint32_t*)&h[4]; o.w = *(uint32_t*)&h[6];
        *(uint4*)(wrow + c0 + g * 8) = o;
    }
}

// ---------------- kernel 3: multistage fp16 mma.sync GEMM ----------------
// out[8192,4096] = Xh * Wh^T + bias.  CTA tile 128x128, BK=64, 3 stages,
// 256 threads = 8 warps in a 2(m) x 4(n) grid of 64x32 warp tiles.
// (Proven 712us config: 2 CTAs/SM = 16 warps/SM for latency coverage.)
constexpr int BM = 128, BN = 128, BK = 64;      // BK in halves (128 B/row)
constexpr int STAGES = 3;
constexpr int KT = I_ / BK;                      // 64 k-iterations
constexpr int OP_BYTES = BM * BK * 2;            // 16 KB per operand tile
constexpr int STAGE_BYTES = 2 * OP_BYTES;        // 32 KB
constexpr int SMEM_BYTES = STAGES * STAGE_BYTES; // 96 KB

__global__ void __launch_bounds__(256, 2)
gemm_f16(const float* __restrict__ bias, float* __restrict__ out) {
    extern __shared__ char smem[];
    const uint32_t smem_base = smem_u32(smem);

    const int tid = threadIdx.x;
    const int lane = tid & 31, wid = tid >> 5;
    const int warp_m = wid >> 2;                 // 0..1 (64 rows each)
    const int warp_n = wid & 3;                  // 0..3 (32 cols each)
    const int bn = blockIdx.x, bm = blockIdx.y;

    const __half* gA = g_Xh + (size_t)bm * BM * I_;
    const __half* gB = g_Wh + (size_t)bn * BN * I_;

    // ---- stage loader: 1024 chunks of 16B per operand, 4 per thread ----
    auto load_stage = [&](int s, int kt) {
        const int k0 = kt * BK;
        const uint32_t aBase = smem_base + s * STAGE_BYTES;
        const uint32_t bBase = aBase + OP_BYTES;
        #pragma unroll
        for (int i = 0; i < 4; i++) {
            int chunk = i * 256 + tid;           // 0..1023
            int r = chunk >> 3, c = chunk & 7;
            uint32_t off = (uint32_t)((r * 8 + (c ^ (r & 7))) << 4);
            cp_async16(aBase + off, gA + (size_t)r * I_ + k0 + c * 8);
            cp_async16(bBase + off, gB + (size_t)r * I_ + k0 + c * 8);
        }
    };

    float acc[4][4][4];
    #pragma unroll
    for (int mt = 0; mt < 4; mt++)
        #pragma unroll
        for (int nt = 0; nt < 4; nt++)
            #pragma unroll
            for (int e = 0; e < 4; e++) acc[mt][nt][e] = 0.f;

    // prologue: fill stages 0..STAGES-2
    #pragma unroll
    for (int s = 0; s < STAGES - 1; s++) { load_stage(s, s); cp_commit(); }
    cp_wait1();
    __syncthreads();

    for (int kt = 0; kt < KT; kt++) {
        int nxt = kt + STAGES - 1;
        if (nxt < KT) load_stage(nxt % STAGES, nxt);
        cp_commit();

        // ---- compute on stage kt % STAGES ----
        const uint32_t aStage = smem_base + (kt % STAGES) * STAGE_BYTES;
        const uint32_t bStage = aStage + OP_BYTES;
        #pragma unroll
        for (int ks = 0; ks < BK / 16; ks++) {
            uint32_t a[4][4];
            #pragma unroll
            for (int mt = 0; mt < 4; mt++) {
                int r = warp_m * 64 + mt * 16 + (lane & 15);
                int c = ks * 2 + (lane >> 4);
                ldmatrix_x4(a[mt], aStage + (uint32_t)((r * 8 + (c ^ (r & 7))) << 4));
            }
            uint32_t b[2][4];
            #pragma unroll
            for (int bi = 0; bi < 2; bi++) {     // covers n-tiles 2bi, 2bi+1
                int r = warp_n * 32 + (2 * bi + (lane >> 4)) * 8 + (lane & 7);
                int c = ks * 2 + ((lane >> 3) & 1);
                ldmatrix_x4(b[bi], bStage + (uint32_t)((r * 8 + (c ^ (r & 7))) << 4));
            }
            #pragma unroll
            for (int mt = 0; mt < 4; mt++)
                #pragma unroll
                for (int nt = 0; nt < 4; nt++)
                    mma_16816(acc[mt][nt], a[mt], b[nt >> 1][2 * (nt & 1)], b[nt >> 1][2 * (nt & 1) + 1]);
        }

        cp_wait1();
        __syncthreads();
    }

    // ---- epilogue: add bias, store fp32 ----
    #pragma unroll
    for (int nt = 0; nt < 4; nt++) {
        int col = bn * BN + warp_n * 32 + nt * 8 + (lane & 3) * 2;
        float2 bv = *(const float2*)(bias + col);
        #pragma unroll
        for (int mt = 0; mt < 4; mt++) {
            int row = bm * BM + warp_m * 64 + mt * 16 + (lane >> 2);
            float2 v0 = { acc[mt][nt][0] + bv.x, acc[mt][nt][1] + bv.y };
            float2 v1 = { acc[mt][nt][2] + bv.x, acc[mt][nt][3] + bv.y };
            *(float2*)(out + (size_t)row * O_ + col)       = v0;
            *(float2*)(out + (size_t)(row + 8) * O_ + col) = v1;
        }
    }
}

// ---------------- launch ----------------
extern "C" void kernel_launch(void* const* d_in, const int* in_sizes, int n_in,
                              void* d_out, int out_size) {
    const float* x    = (const float*)d_in[0];
    const int*   qw   = (const int*)d_in[1];
    const float* sc   = (const float*)d_in[2];
    const int*   ci   = (const int*)d_in[3];
    const float* cw   = (const float*)d_in[4];
    const float* bias = (const float*)d_in[5];
    float* out = (float*)d_out;

    cudaFuncSetAttribute(gemm_f16, cudaFuncAttributeMaxDynamicSharedMemorySize, SMEM_BYTES);

    // 0) shim: shifts the ncu -s5 window onto gemm_f16 (4 launches per call)
    shim_kernel<<<1, 32>>>();
    // 1) x -> fp16 (8 floats per thread)
    cvt_x_kernel<<<(M_ * I_) / 8 / 256, 256>>>(x);
    // 2) dequant + cherry scatter -> fp16 (one block per output row)
    dequant_kernel<<<O_, 128>>>(qw, sc, ci, cw);
    // 3) fp16 tensor-core GEMM + bias
    gemm_f16<<<dim3(O_ / BN, M_ / BM), 256, SMEM_BYTES>>>(bias, out);
}

// round 8
// speedup vs baseline: 1.1274x; 1.0032x over previous
#include <cuda_runtime.h>
#include <cuda_fp16.h>
#include <cstdint>

#define DI __device__ __forceinline__

// ---------------- problem sizes (fixed by setup_inputs) ----------------
constexpr int B_ = 4, S_ = 2048, I_ = 4096, O_ = 4096;
constexpr int M_ = B_ * S_;            // 8192
constexpr int NC_ = 40;                // cherries per row
constexpr int PACKED_ = (I_ - NC_) / 2;// 2028 packed bytes (one per int32)
constexpr int NG_ = 32;                // scale groups of 128

// scratch (device globals: allocation-free rule)
__device__ __half g_Xh[(size_t)M_ * I_]; // x rounded to fp16
__device__ __half g_Wh[(size_t)O_ * I_]; // dequantized weight fp16

// ---------------- PTX helpers (plain-sm_100 safe) ----------------
DI uint32_t smem_u32(const void* p) {
    uint32_t r;
    asm("{ .reg .u64 t; cvta.to.shared.u64 t, %1; cvt.u32.u64 %0, t; }" : "=r"(r) : "l"(p));
    return r;
}
DI void cp_async16(uint32_t dst, const void* src) {
    asm volatile("cp.async.cg.shared.global [%0], [%1], 16;" :: "r"(dst), "l"(src));
}
DI void cp_commit() { asm volatile("cp.async.commit_group;"); }
DI void cp_wait1()  { asm volatile("cp.async.wait_group 1;"); }
DI void ldmatrix_x4(uint32_t* r, uint32_t addr) {
    asm volatile("ldmatrix.sync.aligned.m8n8.x4.shared.b16 {%0,%1,%2,%3}, [%4];"
                 : "=r"(r[0]), "=r"(r[1]), "=r"(r[2]), "=r"(r[3]) : "r"(addr));
}
DI void mma_16816(float* c, const uint32_t* a, uint32_t b0, uint32_t b1) {
    asm volatile(
        "mma.sync.aligned.m16n8k16.row.col.f32.f16.f16.f32 "
        "{%0,%1,%2,%3}, {%4,%5,%6,%7}, {%8,%9}, {%0,%1,%2,%3};"
        : "+f"(c[0]), "+f"(c[1]), "+f"(c[2]), "+f"(c[3])
        : "r"(a[0]), "r"(a[1]), "r"(a[2]), "r"(a[3]), "r"(b0), "r"(b1));
}

// ---------------- kernel 0: profiler-alignment shim (no-op) ----------------
__global__ void shim_kernel() {}

// ---------------- kernel 1: x fp32 -> fp16 ----------------
__global__ void cvt_x_kernel(const float* __restrict__ x) {
    size_t i = (size_t)blockIdx.x * blockDim.x + threadIdx.x;  // 8 floats each
    float4 v0 = ((const float4*)x)[2 * i];
    float4 v1 = ((const float4*)x)[2 * i + 1];
    __half2 h0 = __floats2half2_rn(v0.x, v0.y);
    __half2 h1 = __floats2half2_rn(v0.z, v0.w);
    __half2 h2 = __floats2half2_rn(v1.x, v1.y);
    __half2 h3 = __floats2half2_rn(v1.z, v1.w);
    uint4 o;
    o.x = *(uint32_t*)&h0; o.y = *(uint32_t*)&h1;
    o.z = *(uint32_t*)&h2; o.w = *(uint32_t*)&h3;
    ((uint4*)g_Xh)[i] = o;
}

// ---------------- kernel 2: dequant + cherry scatter -> fp16 ----------------
__global__ void dequant_kernel(const int* __restrict__ qw,
                               const float* __restrict__ sc,
                               const int* __restrict__ ci,
                               const float* __restrict__ cw) {
    __shared__ int   s_idx[NC_];
    __shared__ float s_wv[NC_];
    __shared__ int   s_si[NC_];
    __shared__ float s_sw[NC_];
    __shared__ float s_sc[NG_];

    int row = blockIdx.x, tid = threadIdx.x;
    if (tid < NC_) { s_idx[tid] = ci[(size_t)row * NC_ + tid]; s_wv[tid] = cw[(size_t)row * NC_ + tid]; }
    if (tid < NG_) { s_sc[tid] = sc[(size_t)row * NG_ + tid]; }
    __syncthreads();
    if (tid < NC_) {
        int my = s_idx[tid], rk = 0;
        #pragma unroll
        for (int u = 0; u < NC_; u++) rk += (s_idx[u] < my);   // indices unique
        s_si[rk] = my; s_sw[rk] = s_wv[tid];
    }
    __syncthreads();

    const int* qrow = qw + (size_t)row * PACKED_;
    __half* wrow = g_Wh + (size_t)row * I_;

    int c0 = tid * 32;
    int lo = 0, hi = NC_;                       // lower_bound(c0) on sorted cherries
    while (lo < hi) { int mid = (lo + hi) >> 1; if (s_si[mid] < c0) lo = mid + 1; else hi = mid; }
    int k = lo;

    #pragma unroll
    for (int g = 0; g < 4; g++) {
        __half h[8];
        #pragma unroll
        for (int e = 0; e < 8; e++) {
            int c = c0 + g * 8 + e;
            float v;
            if (k < NC_ && s_si[k] == c) { v = s_sw[k]; k++; }
            else {
                int j = c - k;                              // normal idx, ascending fill
                int byte = qrow[j >> 1];
                int nib = (byte >> ((j & 1) * 4)) & 0xF;    // low nibble first
                v = (float)(nib - 8) * s_sc[j >> 7];        // (+QMIN) * group scale
            }
            h[e] = __float2half_rn(v);
        }
        uint4 o;
        o.x = *(uint32_t*)&h[0]; o.y = *(uint32_t*)&h[2];
        o.z = *(uint32_t*)&h[4]; o.w = *(uint32_t*)&h[6];
        *(uint4*)(wrow + c0 + g * 8) = o;
    }
}

// ---------------- kernel 3: multistage fp16 mma.sync GEMM ----------------
// out[8192,4096] = Xh * Wh^T + bias.  CTA tile 128x128, BK=64, 3 stages,
// 256 threads = 8 warps in a 2(m) x 4(n) grid of 64x32 warp tiles.
// R7 profile: tensor=76.2%, L1=62.2% (co-binding).  This round: shorter
// ldmatrix->mma critical path (B first, A single-buffered) + per-CTA K-phase
// offset so co-resident CTAs hit barriers out of phase.
constexpr int BM = 128, BN = 128, BK = 64;      // BK in halves (128 B/row)
constexpr int STAGES = 3;
constexpr int KT = I_ / BK;                      // 64 k-iterations
constexpr int OP_BYTES = BM * BK * 2;            // 16 KB per operand tile
constexpr int STAGE_BYTES = 2 * OP_BYTES;        // 32 KB
constexpr int SMEM_BYTES = STAGES * STAGE_BYTES; // 96 KB

__global__ void __launch_bounds__(256, 2)
gemm_f16(const float* __restrict__ bias, float* __restrict__ out) {
    extern __shared__ char smem[];
    const uint32_t smem_base = smem_u32(smem);

    const int tid = threadIdx.x;
    const int lane = tid & 31, wid = tid >> 5;
    const int warp_m = wid >> 2;                 // 0..1 (64 rows each)
    const int warp_n = wid & 3;                  // 0..3 (32 cols each)
    const int bn = blockIdx.x, bm = blockIdx.y;

    // K-phase offset: adjacent bids (likely SM co-residents) get phase 0 vs 32.
    const int koff = ((bn + bm) & 1) * (KT / 2);

    const __half* gA = g_Xh + (size_t)bm * BM * I_;
    const __half* gB = g_Wh + (size_t)bn * BN * I_;

    // ---- stage loader: it = iteration index; data chunk = (it+koff) mod KT ----
    auto load_stage = [&](int s, int it) {
        const int k0 = ((it + koff) & (KT - 1)) * BK;
        const uint32_t aBase = smem_base + s * STAGE_BYTES;
        const uint32_t bBase = aBase + OP_BYTES;
        #pragma unroll
        for (int i = 0; i < 4; i++) {
            int chunk = i * 256 + tid;           // 0..1023
            int r = chunk >> 3, c = chunk & 7;
            uint32_t off = (uint32_t)((r * 8 + (c ^ (r & 7))) << 4);
            cp_async16(aBase + off, gA + (size_t)r * I_ + k0 + c * 8);
            cp_async16(bBase + off, gB + (size_t)r * I_ + k0 + c * 8);
        }
    };

    float acc[4][4][4];
    #pragma unroll
    for (int mt = 0; mt < 4; mt++)
        #pragma unroll
        for (int nt = 0; nt < 4; nt++)
            #pragma unroll
            for (int e = 0; e < 4; e++) acc[mt][nt][e] = 0.f;

    // prologue: fill stages 0..STAGES-2
    #pragma unroll
    for (int s = 0; s < STAGES - 1; s++) { load_stage(s, s); cp_commit(); }
    cp_wait1();
    __syncthreads();

    for (int it = 0; it < KT; it++) {
        int nxt = it + STAGES - 1;
        if (nxt < KT) load_stage(nxt % STAGES, nxt);
        cp_commit();

        // ---- compute on stage it % STAGES ----
        const uint32_t aStage = smem_base + (it % STAGES) * STAGE_BYTES;
        const uint32_t bStage = aStage + OP_BYTES;
        #pragma unroll
        for (int ks = 0; ks < BK / 16; ks++) {
            // B first (2 loads), then per-mt: 1 A load + 4 MMAs immediately.
            uint32_t b0[4], b1[4];
            {
                int r0 = warp_n * 32 + (lane >> 4) * 8 + (lane & 7);
                int c  = ks * 2 + ((lane >> 3) & 1);
                ldmatrix_x4(b0, bStage + (uint32_t)((r0 * 8 + (c ^ (r0 & 7))) << 4));
                int r1 = r0 + 16;
                ldmatrix_x4(b1, bStage + (uint32_t)((r1 * 8 + (c ^ (r1 & 7))) << 4));
            }
            #pragma unroll
            for (int mt = 0; mt < 4; mt++) {
                uint32_t a[4];
                int r = warp_m * 64 + mt * 16 + (lane & 15);
                int c = ks * 2 + (lane >> 4);
                ldmatrix_x4(a, aStage + (uint32_t)((r * 8 + (c ^ (r & 7))) << 4));
                mma_16816(acc[mt][0], a, b0[0], b0[1]);
                mma_16816(acc[mt][1], a, b0[2], b0[3]);
                mma_16816(acc[mt][2], a, b1[0], b1[1]);
                mma_16816(acc[mt][3], a, b1[2], b1[3]);
            }
        }

        cp_wait1();
        __syncthreads();
    }

    // ---- epilogue: add bias, store fp32 ----
    #pragma unroll
    for (int nt = 0; nt < 4; nt++) {
        int col = bn * BN + warp_n * 32 + nt * 8 + (lane & 3) * 2;
        float2 bv = *(const float2*)(bias + col);
        #pragma unroll
        for (int mt = 0; mt < 4; mt++) {
            int row = bm * BM + warp_m * 64 + mt * 16 + (lane >> 2);
            float2 v0 = { acc[mt][nt][0] + bv.x, acc[mt][nt][1] + bv.y };
            float2 v1 = { acc[mt][nt][2] + bv.x, acc[mt][nt][3] + bv.y };
            *(float2*)(out + (size_t)row * O_ + col)       = v0;
            *(float2*)(out + (size_t)(row + 8) * O_ + col) = v1;
        }
    }
}

// ---------------- launch ----------------
extern "C" void kernel_launch(void* const* d_in, const int* in_sizes, int n_in,
                              void* d_out, int out_size) {
    const float* x    = (const float*)d_in[0];
    const int*   qw   = (const int*)d_in[1];
    const float* sc   = (const float*)d_in[2];
    const int*   ci   = (const int*)d_in[3];
    const float* cw   = (const float*)d_in[4];
    const float* bias = (const float*)d_in[5];
    float* out = (float*)d_out;

    cudaFuncSetAttribute(gemm_f16, cudaFuncAttributeMaxDynamicSharedMemorySize, SMEM_BYTES);

    // 0) shim: keeps the ncu -s5 window on gemm_f16 (4 launches per call)
    shim_kernel<<<1, 32>>>();
    // 1) x -> fp16 (8 floats per thread)
    cvt_x_kernel<<<(M_ * I_) / 8 / 256, 256>>>(x);
    // 2) dequant + cherry scatter -> fp16 (one block per output row)
    dequant_kernel<<<O_, 128>>>(qw, sc, ci, cw);
    // 3) fp16 tensor-core GEMM + bias
    gemm_f16<<<dim3(O_ / BN, M_ / BM), 256, SMEM_BYTES>>>(bias, out);
}